// round 7
// baseline (speedup 1.0000x reference)
#include <cuda_runtime.h>
#include <cstddef>

#define NN 64
#define G  32          // batches per block
#define TB 192         // 6 role-warps
#define BT 16384       // total batches

// global scratch (coalesced [slot][b])
__device__ float4 gvL[NN * BT];        // normalized prefix vectors, n=1..32
__device__ float4 gvR[NN * BT];        // normalized suffix vectors, n=31..62
__device__ float4 gP1[16 * 4 * BT];    // P1(n)=M[32..n-1], n=33..48
__device__ float4 gP2[15 * 4 * BT];    // P2(n)=M[48..n-1], n=49..63
__device__ float4 gQ1[16 * 4 * BT];    // Q1(n)=M[n+1..31], n=30..15
__device__ float4 gQ2[15 * 4 * BT];    // Q2(n)=M[n+1..15], n=14..0

__device__ __forceinline__ float nan0(float h) {
    unsigned u = __float_as_uint(h);
    return ((u & 0x7fffffffu) > 0x7f800000u) ? 0.0f : h;
}

__global__ __launch_bounds__(TB, 4)
void tdvp_kernel(const float* __restrict__ xg, const float* __restrict__ Ag,
                 const float* __restrict__ Bg, const float* __restrict__ sg,
                 float* __restrict__ yg)
{
    __shared__ float  sA[NN * 32];
    __shared__ float  sB[NN * 68];
    __shared__ float2 sx[G * 65];
    __shared__ float4 sBndL[G];        // raw q32
    __shared__ float4 sBndR[G];        // raw t31
    __shared__ float4 sBnd2L[G];       // raw q48
    __shared__ float4 sBnd2R[G];       // raw t15

    const int tid = threadIdx.x;
    const int b0  = blockIdx.x * G;

    for (int i = tid; i < NN * 32; i += TB) sA[i] = Ag[i];
    for (int i = tid; i < NN * 64; i += TB) sB[(i >> 6) * 68 + (i & 63)] = Bg[i];
    const float2* xv = (const float2*)xg;
    for (int idx = tid; idx < G * NN; idx += TB) {
        float2 v = xv[(size_t)b0 * NN + idx];
        float inv = rsqrtf(v.x * v.x + v.y * v.y);
        v.x *= inv; v.y *= inv;
        sx[(idx >> 6) * 65 + (idx & 63)] = v;
    }
    __syncthreads();

    const int g = tid & 31;
    const int r = tid >> 5;    // 0 fwd-vec, 1 fwd-mat1, 2 fwd-mat2, 3 bwd-vec, 4 bwd-mat1, 5 bwd-mat2
    const int b = b0 + g;

    #define BUILD_M4(nn, R0_, R1_, R2_, R3_)                                   \
    {                                                                          \
        float2 xn_ = sx[g * 65 + (nn)];                                        \
        const float4* ap_ = (const float4*)(sA + (nn) * 32);                   \
        float4 q0_ = ap_[0], q1_ = ap_[1], q2_ = ap_[2], q3_ = ap_[3];         \
        float4 q4_ = ap_[4], q5_ = ap_[5], q6_ = ap_[6], q7_ = ap_[7];         \
        R0_ = make_float4(fmaf(q0_.x, xn_.x, q0_.y * xn_.y),                   \
                          fmaf(q0_.z, xn_.x, q0_.w * xn_.y),                   \
                          fmaf(q1_.x, xn_.x, q1_.y * xn_.y),                   \
                          fmaf(q1_.z, xn_.x, q1_.w * xn_.y));                  \
        R1_ = make_float4(fmaf(q2_.x, xn_.x, q2_.y * xn_.y),                   \
                          fmaf(q2_.z, xn_.x, q2_.w * xn_.y),                   \
                          fmaf(q3_.x, xn_.x, q3_.y * xn_.y),                   \
                          fmaf(q3_.z, xn_.x, q3_.w * xn_.y));                  \
        R2_ = make_float4(fmaf(q4_.x, xn_.x, q4_.y * xn_.y),                   \
                          fmaf(q4_.z, xn_.x, q4_.w * xn_.y),                   \
                          fmaf(q5_.x, xn_.x, q5_.y * xn_.y),                   \
                          fmaf(q5_.z, xn_.x, q5_.w * xn_.y));                  \
        R3_ = make_float4(fmaf(q6_.x, xn_.x, q6_.y * xn_.y),                   \
                          fmaf(q6_.z, xn_.x, q6_.w * xn_.y),                   \
                          fmaf(q7_.x, xn_.x, q7_.y * xn_.y),                   \
                          fmaf(q7_.z, xn_.x, q7_.w * xn_.y));                  \
    }

    // d = v * [M0;M1;M2;M3] (row-vector x matrix), depth-reduced
    #define VMAT(d, v_, M0, M1, M2, M3)                                        \
        d.x = fmaf(v_.x, M0.x, v_.y * M1.x) + fmaf(v_.z, M2.x, v_.w * M3.x);   \
        d.y = fmaf(v_.x, M0.y, v_.y * M1.y) + fmaf(v_.z, M2.y, v_.w * M3.y);   \
        d.z = fmaf(v_.x, M0.z, v_.y * M1.z) + fmaf(v_.z, M2.z, v_.w * M3.z);   \
        d.w = fmaf(v_.x, M0.w, v_.y * M1.w) + fmaf(v_.z, M2.w, v_.w * M3.w);

    // d = [M0;M1;M2;M3] * w (matrix x column-vector)
    #define MATV(d, M0, M1, M2, M3, w_)                                        \
        d.x = fmaf(M0.x, w_.x, M0.y * w_.y) + fmaf(M0.z, w_.z, M0.w * w_.w);   \
        d.y = fmaf(M1.x, w_.x, M1.y * w_.y) + fmaf(M1.z, w_.z, M1.w * w_.w);   \
        d.z = fmaf(M2.x, w_.x, M2.y * w_.y) + fmaf(M2.z, w_.z, M2.w * w_.w);   \
        d.w = fmaf(M3.x, w_.x, M3.y * w_.y) + fmaf(M3.z, w_.z, M3.w * w_.w);

    if (r == 0) {
        // fwd vector chain: n = 1..32
        float4 v = make_float4(1.f, 0.f, 0.f, 0.f);
        #pragma unroll 1
        for (int n = 1; n <= 32; ++n) {
            float4 M0, M1, M2, M3;
            BUILD_M4(n - 1, M0, M1, M2, M3);
            float4 nv; VMAT(nv, v, M0, M1, M2, M3);
            v = nv;
            float d = v.x*v.x + v.y*v.y + v.z*v.z + v.w*v.w;
            float inv = 1.0f / (sqrtf(d) + 1e-6f);
            gvL[n * BT + b] = make_float4(v.x*inv, v.y*inv, v.z*inv, v.w*inv);
        }
        sBndL[g] = v;                              // raw q32
        __syncthreads();
        // pre-output: q48 = q32 * P1(48)
        {
            float4 R0 = gP1[(15 * 4 + 0) * BT + b];
            float4 R1 = gP1[(15 * 4 + 1) * BT + b];
            float4 R2 = gP1[(15 * 4 + 2) * BT + b];
            float4 R3 = gP1[(15 * 4 + 3) * BT + b];
            float4 q; VMAT(q, v, R0, R1, R2, R3);
            sBnd2L[g] = q;
        }
    } else if (r == 1) {
        // fwd mat chain 1: P1(n) = M[32..n-1], n = 33..48
        float4 P0, P1, P2, P3;
        BUILD_M4(32, P0, P1, P2, P3);
        gP1[(0 * 4 + 0) * BT + b] = P0; gP1[(0 * 4 + 1) * BT + b] = P1;
        gP1[(0 * 4 + 2) * BT + b] = P2; gP1[(0 * 4 + 3) * BT + b] = P3;
        #pragma unroll 1
        for (int n = 34; n <= 48; ++n) {
            float4 M0, M1, M2, M3;
            BUILD_M4(n - 1, M0, M1, M2, M3);
            float4 t;
            VMAT(t, P0, M0, M1, M2, M3); P0 = t;
            VMAT(t, P1, M0, M1, M2, M3); P1 = t;
            VMAT(t, P2, M0, M1, M2, M3); P2 = t;
            VMAT(t, P3, M0, M1, M2, M3); P3 = t;
            const int e = n - 33;
            gP1[(e * 4 + 0) * BT + b] = P0; gP1[(e * 4 + 1) * BT + b] = P1;
            gP1[(e * 4 + 2) * BT + b] = P2; gP1[(e * 4 + 3) * BT + b] = P3;
        }
        __syncthreads();
    } else if (r == 2) {
        // fwd mat chain 2: P2(n) = M[48..n-1], n = 49..63
        float4 P0, P1, P2, P3;
        BUILD_M4(48, P0, P1, P2, P3);
        gP2[(0 * 4 + 0) * BT + b] = P0; gP2[(0 * 4 + 1) * BT + b] = P1;
        gP2[(0 * 4 + 2) * BT + b] = P2; gP2[(0 * 4 + 3) * BT + b] = P3;
        #pragma unroll 1
        for (int n = 50; n <= 63; ++n) {
            float4 M0, M1, M2, M3;
            BUILD_M4(n - 1, M0, M1, M2, M3);
            float4 t;
            VMAT(t, P0, M0, M1, M2, M3); P0 = t;
            VMAT(t, P1, M0, M1, M2, M3); P1 = t;
            VMAT(t, P2, M0, M1, M2, M3); P2 = t;
            VMAT(t, P3, M0, M1, M2, M3); P3 = t;
            const int e = n - 49;
            gP2[(e * 4 + 0) * BT + b] = P0; gP2[(e * 4 + 1) * BT + b] = P1;
            gP2[(e * 4 + 2) * BT + b] = P2; gP2[(e * 4 + 3) * BT + b] = P3;
        }
        __syncthreads();
    } else if (r == 3) {
        // bwd vector chain: n = 62..31
        float4 w = make_float4(1.f, 0.f, 0.f, 0.f);
        #pragma unroll 1
        for (int n = 62; n >= 31; --n) {
            float4 M0, M1, M2, M3;
            BUILD_M4(n + 1, M0, M1, M2, M3);
            float4 nw; MATV(nw, M0, M1, M2, M3, w);
            w = nw;
            float d = w.x*w.x + w.y*w.y + w.z*w.z + w.w*w.w;
            float inv = 1.0f / (sqrtf(d) + 1e-6f);
            gvR[n * BT + b] = make_float4(w.x*inv, w.y*inv, w.z*inv, w.w*inv);
        }
        sBndR[g] = w;                              // raw t31
        __syncthreads();
        // pre-output: t15 = Q1(15) * t31
        {
            float4 R0 = gQ1[(15 * 4 + 0) * BT + b];
            float4 R1 = gQ1[(15 * 4 + 1) * BT + b];
            float4 R2 = gQ1[(15 * 4 + 2) * BT + b];
            float4 R3 = gQ1[(15 * 4 + 3) * BT + b];
            float4 t; MATV(t, R0, R1, R2, R3, w);
            sBnd2R[g] = t;
        }
    } else if (r == 4) {
        // bwd mat chain 1: Q1(n) = M[n+1..31], n = 30..15
        float4 Q0, Q1, Q2, Q3;
        BUILD_M4(31, Q0, Q1, Q2, Q3);
        gQ1[(0 * 4 + 0) * BT + b] = Q0; gQ1[(0 * 4 + 1) * BT + b] = Q1;
        gQ1[(0 * 4 + 2) * BT + b] = Q2; gQ1[(0 * 4 + 3) * BT + b] = Q3;
        #pragma unroll 1
        for (int n = 29; n >= 15; --n) {
            float4 M0, M1, M2, M3;
            BUILD_M4(n + 1, M0, M1, M2, M3);
            // Q <- M * Q : row i = M[i].x*Q0 + M[i].y*Q1 + M[i].z*Q2 + M[i].w*Q3
            float4 T0, T1, T2, T3;
            VMAT(T0, M0, Q0, Q1, Q2, Q3);
            VMAT(T1, M1, Q0, Q1, Q2, Q3);
            VMAT(T2, M2, Q0, Q1, Q2, Q3);
            VMAT(T3, M3, Q0, Q1, Q2, Q3);
            Q0 = T0; Q1 = T1; Q2 = T2; Q3 = T3;
            const int e = 30 - n;
            gQ1[(e * 4 + 0) * BT + b] = Q0; gQ1[(e * 4 + 1) * BT + b] = Q1;
            gQ1[(e * 4 + 2) * BT + b] = Q2; gQ1[(e * 4 + 3) * BT + b] = Q3;
        }
        __syncthreads();
    } else {
        // bwd mat chain 2: Q2(n) = M[n+1..15], n = 14..0
        float4 Q0, Q1, Q2, Q3;
        BUILD_M4(15, Q0, Q1, Q2, Q3);
        gQ2[(0 * 4 + 0) * BT + b] = Q0; gQ2[(0 * 4 + 1) * BT + b] = Q1;
        gQ2[(0 * 4 + 2) * BT + b] = Q2; gQ2[(0 * 4 + 3) * BT + b] = Q3;
        #pragma unroll 1
        for (int n = 13; n >= 0; --n) {
            float4 M0, M1, M2, M3;
            BUILD_M4(n + 1, M0, M1, M2, M3);
            float4 T0, T1, T2, T3;
            VMAT(T0, M0, Q0, Q1, Q2, Q3);
            VMAT(T1, M1, Q0, Q1, Q2, Q3);
            VMAT(T2, M2, Q0, Q1, Q2, Q3);
            VMAT(T3, M3, Q0, Q1, Q2, Q3);
            Q0 = T0; Q1 = T1; Q2 = T2; Q3 = T3;
            const int e = 14 - n;
            gQ2[(e * 4 + 0) * BT + b] = Q0; gQ2[(e * 4 + 1) * BT + b] = Q1;
            gQ2[(e * 4 + 2) * BT + b] = Q2; gQ2[(e * 4 + 3) * BT + b] = Q3;
        }
        __syncthreads();
    }
    __syncthreads();   // sBnd2L / sBnd2R visible

    // ---------------- output phase: n = r + 6k ----------------
    {
        const float s = sg[0];
        const float4 qb  = sBndL[g];
        const float4 q48 = sBnd2L[g];
        const float4 tb  = sBndR[g];
        const float4 t15 = sBnd2R[g];

        #pragma unroll 1
        for (int k = 0; k < 11; ++k) {
            const int n = r + 6 * k;
            if (n >= NN) break;

            float4 u;
            if (n == 0) u = make_float4(1.f, 0.f, 0.f, 0.f);
            else if (n <= 32) u = gvL[n * BT + b];
            else {
                float4 raw;
                if (n <= 48) {
                    const int e = n - 33;
                    float4 R0 = gP1[(e * 4 + 0) * BT + b];
                    float4 R1 = gP1[(e * 4 + 1) * BT + b];
                    float4 R2 = gP1[(e * 4 + 2) * BT + b];
                    float4 R3 = gP1[(e * 4 + 3) * BT + b];
                    VMAT(raw, qb, R0, R1, R2, R3);
                } else {
                    const int e = n - 49;
                    float4 R0 = gP2[(e * 4 + 0) * BT + b];
                    float4 R1 = gP2[(e * 4 + 1) * BT + b];
                    float4 R2 = gP2[(e * 4 + 2) * BT + b];
                    float4 R3 = gP2[(e * 4 + 3) * BT + b];
                    VMAT(raw, q48, R0, R1, R2, R3);
                }
                float d = raw.x*raw.x + raw.y*raw.y + raw.z*raw.z + raw.w*raw.w;
                float inv = 1.0f / (sqrtf(d) + 1e-6f);
                u = make_float4(raw.x*inv, raw.y*inv, raw.z*inv, raw.w*inv);
            }

            float4 a;
            if (n == NN - 1) a = make_float4(1.f, 0.f, 0.f, 0.f);
            else if (n >= 31) a = gvR[n * BT + b];
            else {
                float4 raw;
                if (n >= 15) {
                    const int e = 30 - n;
                    float4 R0 = gQ1[(e * 4 + 0) * BT + b];
                    float4 R1 = gQ1[(e * 4 + 1) * BT + b];
                    float4 R2 = gQ1[(e * 4 + 2) * BT + b];
                    float4 R3 = gQ1[(e * 4 + 3) * BT + b];
                    MATV(raw, R0, R1, R2, R3, tb);
                } else {
                    const int e = 14 - n;
                    float4 R0 = gQ2[(e * 4 + 0) * BT + b];
                    float4 R1 = gQ2[(e * 4 + 1) * BT + b];
                    float4 R2 = gQ2[(e * 4 + 2) * BT + b];
                    float4 R3 = gQ2[(e * 4 + 3) * BT + b];
                    MATV(raw, R0, R1, R2, R3, t15);
                }
                float d = raw.x*raw.x + raw.y*raw.y + raw.z*raw.z + raw.w*raw.w;
                float inv = 1.0f / (sqrtf(d) + 1e-6f);
                a = make_float4(raw.x*inv, raw.y*inv, raw.z*inv, raw.w*inv);
            }

            float uu[4] = {u.x, u.y, u.z, u.w};
            float aa[4] = {a.x, a.y, a.z, a.w};
            float H0 = 0.f, H1 = 0.f, H2 = 0.f, H3 = 0.f;
            const float* bb = sB + n * 68;
            #pragma unroll
            for (int i = 0; i < 4; ++i) {
                #pragma unroll
                for (int l = 0; l < 4; ++l) {
                    float w = uu[i] * aa[l];
                    float4 bv = *(const float4*)(bb + i * 16 + l * 4);
                    H0 = fmaf(w, bv.x, H0);
                    H1 = fmaf(w, bv.y, H1);
                    H2 = fmaf(w, bv.z, H2);
                    H3 = fmaf(w, bv.w, H3);
                }
            }

            float f    = sqrtf(H0*H0 + H1*H1 + H2*H2 + H3*H3);
            float invf = s / (f + 1e-6f);
            H0 = fmaxf(nan0(H0 * invf), 0.f);
            H1 = fmaxf(nan0(H1 * invf), 0.f);
            H2 = fmaxf(nan0(H2 * invf), 0.f);
            H3 = fmaxf(nan0(H3 * invf), 0.f);

            float2 xn = sx[g * 65 + n];
            float y0 = fmaf(H0, xn.x, H1 * xn.y);
            float y1 = fmaf(H2, xn.x, H3 * xn.y);
            sx[g * 65 + n] = make_float2(y0, y1);
        }
    }
    __syncthreads();

    float2* yv = (float2*)yg;
    for (int idx = tid; idx < G * NN; idx += TB)
        yv[(size_t)b0 * NN + idx] = sx[(idx >> 6) * 65 + (idx & 63)];
}

extern "C" void kernel_launch(void* const* d_in, const int* in_sizes, int n_in,
                              void* d_out, int out_size) {
    const float* x = (const float*)d_in[0];
    const float* A = (const float*)d_in[1];
    const float* B = (const float*)d_in[2];
    const float* s = (const float*)d_in[3];
    float* y = (float*)d_out;

    const int batch = in_sizes[0] / (NN * 2);   // 16384
    const int grid  = batch / G;                // 512

    tdvp_kernel<<<grid, TB>>>(x, A, B, s, y);
}